// round 10
// baseline (speedup 1.0000x reference)
#include <cuda_runtime.h>
#include <cstdint>

// out[b, bin, d] = ce[chr[b]-1, d]
// BS=512, BINS=2001, DIM=128, N_CHR=24
// Pure store-bandwidth kernel: 512*2001*128*4B = 524.5 MB written.
//
// R8: persistent single-wave grid (148 SMs x 8 CTAs = 1184 CTAs) with a
// grid-stride loop over (b, chunk) work items. Eliminates ~7 waves of CTA
// launch/retire + wave-transition overhead. Store path unchanged
// (.cs float4 + 2x unroll, measured at the 6.4-6.5 TB/s write ceiling).

static constexpr int BS = 512;
static constexpr int BINS = 2001;
static constexpr int DIM = 128;            // 32 float4 per row
static constexpr int THREADS = 256;        // 8 bins per iteration
static constexpr int CHUNKS = 16;          // bin-chunks per sample
static constexpr int BINS_PER_CHUNK = (BINS + CHUNKS - 1) / CHUNKS;  // 126
static constexpr int TOTAL_WORK = BS * CHUNKS;                       // 8192
static constexpr int GRID = 148 * 8;       // exactly one wave at occ=8

__device__ __forceinline__ void stcs4(float4* p, const float4& v) {
    asm volatile("st.global.cs.v4.f32 [%0], {%1, %2, %3, %4};"
                 :: "l"(p), "f"(v.x), "f"(v.y), "f"(v.z), "f"(v.w)
                 : "memory");
}

__global__ __launch_bounds__(THREADS, 8)
void chrom_embed_kernel(const int* __restrict__ chr,
                        const float4* __restrict__ ce4,   // [24, 32] float4
                        float4* __restrict__ out4)        // [512, 2001, 32] float4
{
    const int col    = threadIdx.x & 31;    // float4 column within the row
    const int binOfs = threadIdx.x >> 5;    // 0..7 (warp id)
    constexpr int STEP = THREADS / 32;      // 8 bins per iteration

    for (int work = blockIdx.x; work < TOTAL_WORK; work += GRID) {
        const int b     = work >> 4;        // work / CHUNKS
        const int chunk = work & 15;        // work % CHUNKS

        const int row = chr[b] - 1;         // 0..23 (L1/L2 broadcast hit)
        const float4 v = ce4[row * (DIM / 4) + col];

        const int binStart = chunk * BINS_PER_CHUNK;
        int binEnd = binStart + BINS_PER_CHUNK;
        if (binEnd > BINS) binEnd = BINS;

        float4* __restrict__ dst = out4 + (size_t)b * BINS * (DIM / 4) + col;

        int bin = binStart + binOfs;
        for (; bin + STEP < binEnd; bin += 2 * STEP) {
            stcs4(dst + (size_t)bin * (DIM / 4), v);
            stcs4(dst + (size_t)(bin + STEP) * (DIM / 4), v);
        }
        if (bin < binEnd) {
            stcs4(dst + (size_t)bin * (DIM / 4), v);
        }
    }
}

extern "C" void kernel_launch(void* const* d_in, const int* in_sizes, int n_in,
                              void* d_out, int out_size)
{
    // Inputs per reference order: tensor [512,2001] f32 (unused),
    // chr [512] int32, ce [24,128] f32.
    const int*    chr = (const int*)d_in[1];
    const float4* ce4 = (const float4*)d_in[2];
    float4*       out = (float4*)d_out;

    chrom_embed_kernel<<<GRID, THREADS>>>(chr, ce4, out);
}